// round 12
// baseline (speedup 1.0000x reference)
#include <cuda_runtime.h>
#include <cuda_bf16.h>
#include <math.h>
#include <cstdint>

#define NN   100000
#define NE   640000
#define DD   128
#define NG   512
#define SCAN_B 1024
#define NSB  ((NN + SCAN_B - 1) / SCAN_B)   // 98 scan blocks
#define NTILES ((NN + 255) / 256)           // 391 (256 rows per CTA)

// ---------------- scratch (no allocations allowed) ----------------
__device__ uint2 g_hwA[(size_t)NN * 32];    // h@W ping (bf16x2, 25.6MB)
__device__ uint2 g_hwB[(size_t)NN * 32];    // h@W pong
__device__ float g_dinv[NN];
__device__ float g_dinv2[NN];
__device__ int   g_cnt [NN];
__device__ int   g_off [NN + 1];
__device__ int   g_cursor[NN];
__device__ int   g_csrc[NE];
__device__ float g_cw  [NE];
__device__ int   g_bsum[NSB];
__device__ float g_pooled[NG * DD];
// packed W fragments: [layer][n(128)][kk(8)][q(4)] uint4 = {hi@kb, hi@kb+4, lo@kb, lo@kb+4}
__device__ uint4 g_wpack[4 * 128 * 8 * 4];

// ---------------- smem layouts ----------------
#define WPAD 36                              // uint4 per W n-row (padded from 32)
#define APAD 68                              // uint32 per A row (padded from 64)
#define SM_A_WORDS (256 * APAD)              // 17408 words = 69632 B
#define SM_W_OFF   (SM_A_WORDS * 4)          // byte offset of W tile
#define SMEM_FUSED (SM_W_OFF + 128 * WPAD * 16)   // 69632 + 73728 = 143360
#define SMEM_G0    (128 * WPAD * 16)         // gemm0: W only (73728)

__device__ __forceinline__ void mma_bf16(float c[4], uint32_t a0, uint32_t a1,
                                         uint32_t a2, uint32_t a3,
                                         uint32_t b0, uint32_t b1) {
    asm volatile(
        "mma.sync.aligned.m16n8k16.row.col.f32.bf16.bf16.f32 "
        "{%0,%1,%2,%3}, {%4,%5,%6,%7}, {%8,%9}, {%0,%1,%2,%3};"
        : "+f"(c[0]), "+f"(c[1]), "+f"(c[2]), "+f"(c[3])
        : "r"(a0), "r"(a1), "r"(a2), "r"(a3), "r"(b0), "r"(b1));
}

__device__ __forceinline__ uint32_t bf2_of(float a, float b) {
    __nv_bfloat162 t = __float22bfloat162_rn(make_float2(a, b));
    return *reinterpret_cast<uint32_t*>(&t);
}
__device__ __forceinline__ float2 bf2f(uint32_t u) {
    __nv_bfloat162 h = *reinterpret_cast<__nv_bfloat162*>(&u);
    return __bfloat1622float2(h);
}

// ---- shared agg core: accumulate node n's neighbors into a0..a3 (lane-sliced) ----
__device__ __forceinline__ void agg_node(const uint2* __restrict__ hwb, int n, int lane,
                                         float& a0, float& a1, float& a2, float& a3)
{
    uint2 sv = __ldg(&hwb[(size_t)n * 32 + lane]);
    float2 s0 = bf2f(sv.x), s1 = bf2f(sv.y);
    float w = g_dinv2[n];
    a0 = s0.x * w; a1 = s0.y * w; a2 = s1.x * w; a3 = s1.y * w;
    int i = g_off[n], end = g_off[n + 1];
    for (; i + 4 <= end; i += 4) {
        int   i0 = g_csrc[i],     i1 = g_csrc[i + 1];
        int   i2 = g_csrc[i + 2], i3 = g_csrc[i + 3];
        float w0 = g_cw[i],     w1 = g_cw[i + 1];
        float w2 = g_cw[i + 2], w3 = g_cw[i + 3];
        uint2 v0 = __ldg(&hwb[(size_t)i0 * 32 + lane]);
        uint2 v1 = __ldg(&hwb[(size_t)i1 * 32 + lane]);
        uint2 v2 = __ldg(&hwb[(size_t)i2 * 32 + lane]);
        uint2 v3 = __ldg(&hwb[(size_t)i3 * 32 + lane]);
        float2 f;
        f = bf2f(v0.x); a0 = fmaf(w0, f.x, a0); a1 = fmaf(w0, f.y, a1);
        f = bf2f(v0.y); a2 = fmaf(w0, f.x, a2); a3 = fmaf(w0, f.y, a3);
        f = bf2f(v1.x); a0 = fmaf(w1, f.x, a0); a1 = fmaf(w1, f.y, a1);
        f = bf2f(v1.y); a2 = fmaf(w1, f.x, a2); a3 = fmaf(w1, f.y, a3);
        f = bf2f(v2.x); a0 = fmaf(w2, f.x, a0); a1 = fmaf(w2, f.y, a1);
        f = bf2f(v2.y); a2 = fmaf(w2, f.x, a2); a3 = fmaf(w2, f.y, a3);
        f = bf2f(v3.x); a0 = fmaf(w3, f.x, a0); a1 = fmaf(w3, f.y, a1);
        f = bf2f(v3.y); a2 = fmaf(w3, f.x, a2); a3 = fmaf(w3, f.y, a3);
    }
    for (; i < end; i++) {
        int   sn = g_csrc[i];
        float we = g_cw[i];
        uint2 v  = __ldg(&hwb[(size_t)sn * 32 + lane]);
        float2 f0 = bf2f(v.x), f1 = bf2f(v.y);
        a0 = fmaf(we, f0.x, a0);
        a1 = fmaf(we, f0.y, a1);
        a2 = fmaf(we, f1.x, a2);
        a3 = fmaf(we, f1.y, a3);
    }
}

// ---------------- main-stream init: W pack + zero pooled ----------------
__global__ void k_wpack(const float* __restrict__ convW) {
    int idx = blockIdx.x * 256 + threadIdx.x;
    if (idx < NG * DD) g_pooled[idx] = 0.f;
    if (idx < 16384) {
        int q  = idx & 3;
        int kk = (idx >> 2) & 7;
        int n  = (idx >> 5) & 127;
        int l  = idx >> 12;
        int k0 = kk * 16 + q * 2;
        const float* Wl = convW + (size_t)l * 16384;
        float w00 = Wl[(size_t)(k0    ) * 128 + n], w01 = Wl[(size_t)(k0 + 1) * 128 + n];
        float w10 = Wl[(size_t)(k0 + 8) * 128 + n], w11 = Wl[(size_t)(k0 + 9) * 128 + n];
        __nv_bfloat162 h0 = __float22bfloat162_rn(make_float2(w00, w01));
        __nv_bfloat162 h1 = __float22bfloat162_rn(make_float2(w10, w11));
        float2 f0 = __bfloat1622float2(h0), f1 = __bfloat1622float2(h1);
        uint4 v;
        v.x = *reinterpret_cast<uint32_t*>(&h0);
        v.y = *reinterpret_cast<uint32_t*>(&h1);
        v.z = bf2_of(w00 - f0.x, w01 - f0.y);
        v.w = bf2_of(w10 - f1.x, w11 - f1.y);
        g_wpack[idx] = v;
    }
}

// ---------------- side-stream CSR build ----------------
__global__ void k_cntzero() {
    int n = blockIdx.x * blockDim.x + threadIdx.x;
    if (n < NN) g_cnt[n] = 0;
}
__global__ void k_cnt(const int* __restrict__ dst) {
    int e = blockIdx.x * blockDim.x + threadIdx.x;
    if (e < NE) atomicAdd(&g_cnt[dst[e]], 1);
}
__global__ __launch_bounds__(SCAN_B) void k_scan1() {
    __shared__ int s[SCAN_B];
    int t = threadIdx.x;
    int i = blockIdx.x * SCAN_B + t;
    int v = (i < NN) ? g_cnt[i] : 0;
    if (i < NN) {
        float deg = (float)(v + 1);
        g_dinv[i]  = rsqrtf(deg);
        g_dinv2[i] = 1.0f / deg;
    }
    s[t] = v;
    __syncthreads();
    #pragma unroll
    for (int o = 1; o < SCAN_B; o <<= 1) {
        int x = (t >= o) ? s[t - o] : 0;
        __syncthreads();
        s[t] += x;
        __syncthreads();
    }
    if (i < NN) g_cnt[i] = s[t];
    if (t == SCAN_B - 1) g_bsum[blockIdx.x] = s[t];
}
__global__ __launch_bounds__(SCAN_B) void k_scan3() {
    __shared__ int partial[32];
    __shared__ int pre_s;
    int t = threadIdx.x;
    int v = (t < NSB && t < blockIdx.x) ? g_bsum[t] : 0;
    #pragma unroll
    for (int o = 16; o > 0; o >>= 1) v += __shfl_down_sync(0xffffffffu, v, o);
    if ((t & 31) == 0) partial[t >> 5] = v;
    __syncthreads();
    if (t == 0) {
        int s = 0;
        #pragma unroll
        for (int w = 0; w < SCAN_B / 32; w++) s += partial[w];
        pre_s = s;
    }
    __syncthreads();
    int pre = pre_s;
    int i = blockIdx.x * SCAN_B + t;
    if (i < NN) {
        int incl = g_cnt[i] + pre;
        g_off[i + 1] = incl;
        if (i + 1 < NN) g_cursor[i + 1] = incl;
        if (i == 0) { g_off[0] = 0; g_cursor[0] = 0; }
    }
}
__global__ void k_scatter(const int* __restrict__ src, const int* __restrict__ dst) {
    int e = blockIdx.x * blockDim.x + threadIdx.x;
    if (e < NE) {
        int s = src[e], t = dst[e];
        int p = atomicAdd(&g_cursor[t], 1);
        g_csrc[p] = s;
        g_cw[p]   = g_dinv[s] * g_dinv[t];
    }
}

// ============ gemm0: hw[M,128](bf16) = x @ W0, x fp32 (3-term split) ============
__global__ __launch_bounds__(512, 1) void k_gemm0(
    const float* __restrict__ A, const uint4* __restrict__ wp,
    uint32_t* __restrict__ outb, int M)
{
    extern __shared__ char smem[];
    uint4* Wp = reinterpret_cast<uint4*>(smem);
    int tid  = threadIdx.x;
    int wid  = tid >> 5;
    int lane = tid & 31;
    int m0   = blockIdx.x * 256;

    #pragma unroll
    for (int i = 0; i < 8; i++) {
        int idx = tid + i * 512;
        int n = idx >> 5, r = idx & 31;
        Wp[n * WPAD + r] = wp[idx];
    }
    __syncthreads();

    int fr = lane >> 2, q = lane & 3;
    int r0 = m0 + wid * 16 + fr;
    int r1 = r0 + 8;
    bool ok0 = r0 < M, ok1 = r1 < M;

    float acc[16][4];
    #pragma unroll
    for (int ni = 0; ni < 16; ni++)
        #pragma unroll
        for (int p = 0; p < 4; p++) acc[ni][p] = 0.f;

    const float2* A2 = reinterpret_cast<const float2*>(A);

    #pragma unroll
    for (int kk = 0; kk < 8; kk++) {
        int kw = kk * 8 + q;
        float2 v00 = make_float2(0.f, 0.f), v01 = v00, v10 = v00, v11 = v00;
        if (ok0) { v00 = A2[(size_t)r0 * 64 + kw]; v01 = A2[(size_t)r0 * 64 + kw + 4]; }
        if (ok1) { v10 = A2[(size_t)r1 * 64 + kw]; v11 = A2[(size_t)r1 * 64 + kw + 4]; }
        uint32_t ah[4], al[4];
        __nv_bfloat162 h; float2 f;
        h = __float22bfloat162_rn(v00); f = __bfloat1622float2(h);
        ah[0] = *reinterpret_cast<uint32_t*>(&h); al[0] = bf2_of(v00.x - f.x, v00.y - f.y);
        h = __float22bfloat162_rn(v10); f = __bfloat1622float2(h);
        ah[1] = *reinterpret_cast<uint32_t*>(&h); al[1] = bf2_of(v10.x - f.x, v10.y - f.y);
        h = __float22bfloat162_rn(v01); f = __bfloat1622float2(h);
        ah[2] = *reinterpret_cast<uint32_t*>(&h); al[2] = bf2_of(v01.x - f.x, v01.y - f.y);
        h = __float22bfloat162_rn(v11); f = __bfloat1622float2(h);
        ah[3] = *reinterpret_cast<uint32_t*>(&h); al[3] = bf2_of(v11.x - f.x, v11.y - f.y);
        #pragma unroll
        for (int ni = 0; ni < 16; ni++) {
            int n = ni * 8 + fr;
            uint4 b = Wp[n * WPAD + kk * 4 + q];
            mma_bf16(acc[ni], ah[0], ah[1], ah[2], ah[3], b.x, b.y);
            mma_bf16(acc[ni], ah[0], ah[1], ah[2], ah[3], b.z, b.w);
            mma_bf16(acc[ni], al[0], al[1], al[2], al[3], b.x, b.y);
        }
    }
    #pragma unroll
    for (int ni = 0; ni < 16; ni++) {
        int cw = ni * 4 + q;
        if (ok0) outb[(size_t)r0 * 64 + cw] = bf2_of(acc[ni][0], acc[ni][1]);
        if (ok1) outb[(size_t)r1 * 64 + cw] = bf2_of(acc[ni][2], acc[ni][3]);
    }
}

// ============ fused agg_l + gemm_{l+1}: hw_out = relu(agg(hw_in)+b) @ W ============
__global__ __launch_bounds__(512, 1) void k_agg_gemm(
    const uint2* __restrict__ hwin, const float* __restrict__ bias,
    const uint4* __restrict__ wp, uint32_t* __restrict__ outb)
{
    extern __shared__ char smem[];
    uint32_t* As = reinterpret_cast<uint32_t*>(smem);
    uint4*    Wp = reinterpret_cast<uint4*>(smem + SM_W_OFF);
    int tid  = threadIdx.x;
    int wid  = tid >> 5;
    int lane = tid & 31;
    int m0   = blockIdx.x * 256;

    // stage W tile
    #pragma unroll
    for (int i = 0; i < 8; i++) {
        int idx = tid + i * 512;
        int n = idx >> 5, r = idx & 31;
        Wp[n * WPAD + r] = wp[idx];
    }

    // agg phase: each warp aggregates 16 nodes into smem A tile (bf16, bias+relu)
    float4 b4 = reinterpret_cast<const float4*>(bias)[lane];
    #pragma unroll 1
    for (int i = 0; i < 16; i++) {
        int lr = wid * 16 + i;
        int n  = m0 + lr;
        uint2 o = make_uint2(0u, 0u);
        if (n < NN) {
            float a0, a1, a2, a3;
            agg_node(hwin, n, lane, a0, a1, a2, a3);
            o.x = bf2_of(fmaxf(a0 + b4.x, 0.f), fmaxf(a1 + b4.y, 0.f));
            o.y = bf2_of(fmaxf(a2 + b4.z, 0.f), fmaxf(a3 + b4.w, 0.f));
        }
        *reinterpret_cast<uint2*>(&As[lr * APAD + lane * 2]) = o;
    }
    __syncthreads();

    // GEMM phase: A from smem (2-term split: A exact bf16)
    int fr = lane >> 2, q = lane & 3;
    int lr0 = wid * 16 + fr;
    int r0  = m0 + lr0;
    int r1  = r0 + 8;
    bool ok0 = r0 < NN, ok1 = r1 < NN;

    float acc[16][4];
    #pragma unroll
    for (int ni = 0; ni < 16; ni++)
        #pragma unroll
        for (int p = 0; p < 4; p++) acc[ni][p] = 0.f;

    #pragma unroll
    for (int kk = 0; kk < 8; kk++) {
        int kw = kk * 8 + q;
        uint32_t ah0 = As[lr0 * APAD + kw];
        uint32_t ah1 = As[(lr0 + 8) * APAD + kw];
        uint32_t ah2 = As[lr0 * APAD + kw + 4];
        uint32_t ah3 = As[(lr0 + 8) * APAD + kw + 4];
        #pragma unroll
        for (int ni = 0; ni < 16; ni++) {
            int n = ni * 8 + fr;
            uint4 b = Wp[n * WPAD + kk * 4 + q];
            mma_bf16(acc[ni], ah0, ah1, ah2, ah3, b.x, b.y);
            mma_bf16(acc[ni], ah0, ah1, ah2, ah3, b.z, b.w);
        }
    }
    #pragma unroll
    for (int ni = 0; ni < 16; ni++) {
        int cw = ni * 4 + q;
        if (ok0) outb[(size_t)r0 * 64 + cw] = bf2_of(acc[ni][0], acc[ni][1]);
        if (ok1) outb[(size_t)r1 * 64 + cw] = bf2_of(acc[ni][2], acc[ni][3]);
    }
}

// ============ fused agg3 + pool: pooled[g] += relu(agg(hw)+b), batch sorted ============
__global__ __launch_bounds__(256) void k_agg_pool(
    const uint2* __restrict__ hwin, const float* __restrict__ bias,
    const int* __restrict__ batch)
{
    int wid  = threadIdx.x >> 5;
    int lane = threadIdx.x & 31;
    int n0   = (blockIdx.x * 8 + wid) * 16;
    if (n0 >= NN) return;
    float4 b4 = reinterpret_cast<const float4*>(bias)[lane];
    float p0 = 0.f, p1 = 0.f, p2 = 0.f, p3 = 0.f;
    int gprev = batch[n0];
    #pragma unroll 1
    for (int i = 0; i < 16; i++) {
        int n = n0 + i;
        if (n >= NN) break;
        float a0, a1, a2, a3;
        agg_node(hwin, n, lane, a0, a1, a2, a3);
        a0 = fmaxf(a0 + b4.x, 0.f);
        a1 = fmaxf(a1 + b4.y, 0.f);
        a2 = fmaxf(a2 + b4.z, 0.f);
        a3 = fmaxf(a3 + b4.w, 0.f);
        int g = batch[n];
        if (g != gprev) {
            float* dp = &g_pooled[gprev * 128 + lane * 4];
            atomicAdd(dp + 0, p0); atomicAdd(dp + 1, p1);
            atomicAdd(dp + 2, p2); atomicAdd(dp + 3, p3);
            p0 = p1 = p2 = p3 = 0.f;
            gprev = g;
        }
        p0 += a0; p1 += a1; p2 += a2; p3 += a3;
    }
    float* dp = &g_pooled[gprev * 128 + lane * 4];
    atomicAdd(dp + 0, p0); atomicAdd(dp + 1, p1);
    atomicAdd(dp + 2, p2); atomicAdd(dp + 3, p3);
}

// ---------------- fused MLP head ----------------
__global__ void k_head(const float* __restrict__ W1, const float* __restrict__ b1,
                       const float* __restrict__ W2, const float* __restrict__ b2,
                       const float* __restrict__ W3, const float* __restrict__ b3,
                       float* __restrict__ out)
{
    __shared__ float buf[128];
    __shared__ float partial[4];
    int g = blockIdx.x, c = threadIdx.x;
    buf[c] = g_pooled[g * 128 + c];
    __syncthreads();
    float acc = b1[c];
    #pragma unroll 8
    for (int k = 0; k < 128; k++)
        acc = fmaf(buf[k], W1[k * 128 + c], acc);
    float z1 = fmaxf(acc, 0.f);
    __syncthreads();
    buf[c] = z1;
    __syncthreads();
    acc = b2[c];
    #pragma unroll 8
    for (int k = 0; k < 128; k++)
        acc = fmaf(buf[k], W2[k * 128 + c], acc);
    float z2 = fmaxf(acc, 0.f);
    float v = z2 * W3[c];
    #pragma unroll
    for (int o = 16; o > 0; o >>= 1) v += __shfl_down_sync(0xffffffffu, v, o);
    if ((c & 31) == 0) partial[c >> 5] = v;
    __syncthreads();
    if (c == 0) {
        float s = partial[0] + partial[1] + partial[2] + partial[3] + b3[0];
        out[g] = 1.f / (1.f + expf(-s));
    }
}

// ---------------- launch ----------------
extern "C" void kernel_launch(void* const* d_in, const int* in_sizes, int n_in,
                              void* d_out, int out_size)
{
    const float* x     = (const float*)d_in[0];
    const int*   ei    = (const int*)d_in[1];     // int32 (JAX x64 disabled)
    const int*   src   = ei;
    const int*   dst   = ei + NE;
    const int*   batch = (const int*)d_in[2];
    const float* convW = (const float*)d_in[3];
    const float* convB = (const float*)d_in[4];
    const float* W1    = (const float*)d_in[5];
    const float* b1    = (const float*)d_in[6];
    const float* W2    = (const float*)d_in[7];
    const float* b2    = (const float*)d_in[8];
    const float* W3    = (const float*)d_in[9];
    const float* b3    = (const float*)d_in[10];
    float* out = (float*)d_out;

    uint2 *hwA, *hwB;  uint4* wpk;
    cudaGetSymbolAddress((void**)&hwA, g_hwA);
    cudaGetSymbolAddress((void**)&hwB, g_hwB);
    cudaGetSymbolAddress((void**)&wpk, g_wpack);

    static cudaStream_t s2;
    static cudaEvent_t evFork, evJoin;
    static bool once = false;
    if (!once) {
        cudaFuncSetAttribute(k_gemm0,    cudaFuncAttributeMaxDynamicSharedMemorySize, SMEM_G0);
        cudaFuncSetAttribute(k_agg_gemm, cudaFuncAttributeMaxDynamicSharedMemorySize, SMEM_FUSED);
        cudaStreamCreateWithFlags(&s2, cudaStreamNonBlocking);
        cudaEventCreateWithFlags(&evFork, cudaEventDisableTiming);
        cudaEventCreateWithFlags(&evJoin, cudaEventDisableTiming);
        once = true;
    }

    // ---- fork: CSR build on side stream, W pack + gemm0 on main ----
    cudaEventRecord(evFork, 0);
    cudaStreamWaitEvent(s2, evFork, 0);

    k_cntzero<<<(NN + 255) / 256, 256, 0, s2>>>();
    k_cnt    <<<(NE + 255) / 256, 256, 0, s2>>>(dst);
    k_scan1  <<<NSB, SCAN_B, 0, s2>>>();
    k_scan3  <<<NSB, SCAN_B, 0, s2>>>();
    k_scatter<<<(NE + 255) / 256, 256, 0, s2>>>(src, dst);
    cudaEventRecord(evJoin, s2);

    k_wpack<<<(NG * DD + 255) / 256, 256>>>(convW);
    k_gemm0<<<NTILES, 512, SMEM_G0>>>(x, wpk, reinterpret_cast<uint32_t*>(hwA), NN);

    // ---- join, then fused layer chain ----
    cudaStreamWaitEvent(0, evJoin, 0);
    // layer l: agg_{l-1} + gemm_l  (l = 1..3), ping-pong hwA <-> hwB
    k_agg_gemm<<<NTILES, 512, SMEM_FUSED>>>(hwA, convB, wpk + 4096,
                                            reinterpret_cast<uint32_t*>(hwB));
    k_agg_gemm<<<NTILES, 512, SMEM_FUSED>>>(hwB, convB + DD, wpk + 2 * 4096,
                                            reinterpret_cast<uint32_t*>(hwA));
    k_agg_gemm<<<NTILES, 512, SMEM_FUSED>>>(hwA, convB + 2 * DD, wpk + 3 * 4096,
                                            reinterpret_cast<uint32_t*>(hwB));
    // final: agg3 + pool fused
    k_agg_pool<<<(NN + 127) / 128, 256>>>(hwB, convB + 3 * DD, batch);

    // ---- MLP head ----
    k_head<<<NG, 128>>>(W1, b1, W2, b2, W3, b3, out);
}

// round 13
// speedup vs baseline: 1.3350x; 1.3350x over previous
#include <cuda_runtime.h>
#include <cuda_bf16.h>
#include <math.h>
#include <cstdint>

#define NN   100000
#define NE   640000
#define DD   128
#define NG   512
#define SCAN_B 1024
#define NSB  ((NN + SCAN_B - 1) / SCAN_B)   // 98 scan blocks
#define NTILES ((NN + 255) / 256)           // 391 (256 rows per CTA)

// ---------------- scratch (no allocations allowed) ----------------
__device__ uint2 g_hwb[(size_t)NN * 32];    // h@W in bf16x2 (25.6MB)
__device__ uint2 g_hbf[(size_t)NN * 32];    // relu(agg+b) in bf16x2 (25.6MB)
__device__ float g_dinv[NN];
__device__ float g_dinv2[NN];
__device__ int   g_cnt [NN];
__device__ int   g_off [NN + 1];
__device__ int   g_cursor[NN];
__device__ int   g_csrc[NE];
__device__ float g_cw  [NE];
__device__ int   g_bsum[NSB];
__device__ int   g_goff[NG + 1];            // per-graph node ranges (batch sorted)
// packed W fragments: [layer][n(128)][kk(8)][q(4)] uint4 = {hi@kb, hi@kb+4, lo@kb, lo@kb+4}
__device__ uint4 g_wpack[4 * 128 * 8 * 4];

// ---------------- smem layout for MMA GEMM ----------------
#define WPAD 36                          // uint4 per n-row in smem (padded from 32)
#define SMEM_MMA (128 * WPAD * 16)       // 73728

__device__ __forceinline__ void mma_bf16(float c[4], uint32_t a0, uint32_t a1,
                                         uint32_t a2, uint32_t a3,
                                         uint32_t b0, uint32_t b1) {
    asm volatile(
        "mma.sync.aligned.m16n8k16.row.col.f32.bf16.bf16.f32 "
        "{%0,%1,%2,%3}, {%4,%5,%6,%7}, {%8,%9}, {%0,%1,%2,%3};"
        : "+f"(c[0]), "+f"(c[1]), "+f"(c[2]), "+f"(c[3])
        : "r"(a0), "r"(a1), "r"(a2), "r"(a3), "r"(b0), "r"(b1));
}

__device__ __forceinline__ uint32_t bf2_of(float a, float b) {
    __nv_bfloat162 t = __float22bfloat162_rn(make_float2(a, b));
    return *reinterpret_cast<uint32_t*>(&t);
}
__device__ __forceinline__ float2 bf2f(uint32_t u) {
    __nv_bfloat162 h = *reinterpret_cast<__nv_bfloat162*>(&u);
    return __bfloat1622float2(h);
}

// ---------------- main-stream init: W pack ----------------
__global__ void k_wpack(const float* __restrict__ convW) {
    int idx = blockIdx.x * 256 + threadIdx.x;
    if (idx < 16384) {
        int q  = idx & 3;
        int kk = (idx >> 2) & 7;
        int n  = (idx >> 5) & 127;
        int l  = idx >> 12;
        int k0 = kk * 16 + q * 2;
        const float* Wl = convW + (size_t)l * 16384;
        float w00 = Wl[(size_t)(k0    ) * 128 + n], w01 = Wl[(size_t)(k0 + 1) * 128 + n];
        float w10 = Wl[(size_t)(k0 + 8) * 128 + n], w11 = Wl[(size_t)(k0 + 9) * 128 + n];
        __nv_bfloat162 h0 = __float22bfloat162_rn(make_float2(w00, w01));
        __nv_bfloat162 h1 = __float22bfloat162_rn(make_float2(w10, w11));
        float2 f0 = __bfloat1622float2(h0), f1 = __bfloat1622float2(h1);
        uint4 v;
        v.x = *reinterpret_cast<uint32_t*>(&h0);
        v.y = *reinterpret_cast<uint32_t*>(&h1);
        v.z = bf2_of(w00 - f0.x, w01 - f0.y);
        v.w = bf2_of(w10 - f1.x, w11 - f1.y);
        g_wpack[idx] = v;
    }
}

// ---------------- side-stream CSR build + graph offsets ----------------
__global__ void k_cntzero() {
    int n = blockIdx.x * blockDim.x + threadIdx.x;
    if (n < NN) g_cnt[n] = 0;
}
__global__ void k_cnt(const int* __restrict__ dst) {
    int e = blockIdx.x * blockDim.x + threadIdx.x;
    if (e < NE) atomicAdd(&g_cnt[dst[e]], 1);
}
// per-graph node ranges from sorted batch
__global__ void k_goff(const int* __restrict__ batch) {
    int n = blockIdx.x * blockDim.x + threadIdx.x;
    if (n > NN) return;
    int glo = (n == 0)  ? 0  : batch[n - 1] + 1;
    int ghi = (n == NN) ? NG : batch[n];
    for (int g = glo; g <= ghi; g++) g_goff[g] = n;
}
__global__ __launch_bounds__(SCAN_B) void k_scan1() {
    __shared__ int s[SCAN_B];
    int t = threadIdx.x;
    int i = blockIdx.x * SCAN_B + t;
    int v = (i < NN) ? g_cnt[i] : 0;
    if (i < NN) {
        float deg = (float)(v + 1);
        g_dinv[i]  = rsqrtf(deg);
        g_dinv2[i] = 1.0f / deg;
    }
    s[t] = v;
    __syncthreads();
    #pragma unroll
    for (int o = 1; o < SCAN_B; o <<= 1) {
        int x = (t >= o) ? s[t - o] : 0;
        __syncthreads();
        s[t] += x;
        __syncthreads();
    }
    if (i < NN) g_cnt[i] = s[t];
    if (t == SCAN_B - 1) g_bsum[blockIdx.x] = s[t];
}
__global__ __launch_bounds__(SCAN_B) void k_scan3() {
    __shared__ int partial[32];
    __shared__ int pre_s;
    int t = threadIdx.x;
    int v = (t < NSB && t < blockIdx.x) ? g_bsum[t] : 0;
    #pragma unroll
    for (int o = 16; o > 0; o >>= 1) v += __shfl_down_sync(0xffffffffu, v, o);
    if ((t & 31) == 0) partial[t >> 5] = v;
    __syncthreads();
    if (t == 0) {
        int s = 0;
        #pragma unroll
        for (int w = 0; w < SCAN_B / 32; w++) s += partial[w];
        pre_s = s;
    }
    __syncthreads();
    int pre = pre_s;
    int i = blockIdx.x * SCAN_B + t;
    if (i < NN) {
        int incl = g_cnt[i] + pre;
        g_off[i + 1] = incl;
        if (i + 1 < NN) g_cursor[i + 1] = incl;
        if (i == 0) { g_off[0] = 0; g_cursor[0] = 0; }
    }
}
__global__ void k_scatter(const int* __restrict__ src, const int* __restrict__ dst) {
    int e = blockIdx.x * blockDim.x + threadIdx.x;
    if (e < NE) {
        int s = src[e], t = dst[e];
        int p = atomicAdd(&g_cursor[t], 1);
        g_csrc[p] = s;
        g_cw[p]   = g_dinv[s] * g_dinv[t];
    }
}

// ============ tensor-core GEMM: hwb[M,128](bf16) = A @ W, 256 rows/CTA ============
// FUSE=0: A = fp32 input x (3-term split). FUSE=1: A = hbf (bf16, 2-term split).
template <int FUSE>
__global__ __launch_bounds__(512, 1) void k_gemm_mma(
    const void* __restrict__ Ain, const uint4* __restrict__ wp,
    uint32_t* __restrict__ outb, int M)
{
    extern __shared__ char smem[];
    uint4* Wp = reinterpret_cast<uint4*>(smem);
    int tid  = threadIdx.x;
    int wid  = tid >> 5;
    int lane = tid & 31;
    int m0   = blockIdx.x * 256;

    #pragma unroll
    for (int i = 0; i < 8; i++) {
        int idx = tid + i * 512;           // 4096 uint4
        int n = idx >> 5, r = idx & 31;
        Wp[n * WPAD + r] = wp[idx];
    }
    __syncthreads();

    int fr = lane >> 2;                    // 0..7
    int q  = lane & 3;                     // 0..3
    int r0 = m0 + wid * 16 + fr;
    int r1 = r0 + 8;
    bool ok0 = r0 < M, ok1 = r1 < M;

    float acc[16][4];
    #pragma unroll
    for (int ni = 0; ni < 16; ni++)
        #pragma unroll
        for (int p = 0; p < 4; p++) acc[ni][p] = 0.f;

    #pragma unroll
    for (int kk = 0; kk < 8; kk++) {
        int kw = kk * 8 + q;
        uint32_t ah[4], al[4];
        if (FUSE) {
            const uint32_t* H = reinterpret_cast<const uint32_t*>(Ain);
            ah[0] = ok0 ? H[(size_t)r0 * 64 + kw]     : 0u;
            ah[2] = ok0 ? H[(size_t)r0 * 64 + kw + 4] : 0u;
            ah[1] = ok1 ? H[(size_t)r1 * 64 + kw]     : 0u;
            ah[3] = ok1 ? H[(size_t)r1 * 64 + kw + 4] : 0u;
        } else {
            const float2* A2 = reinterpret_cast<const float2*>(Ain);
            float2 v00 = make_float2(0.f, 0.f), v01 = v00, v10 = v00, v11 = v00;
            if (ok0) { v00 = A2[(size_t)r0 * 64 + kw]; v01 = A2[(size_t)r0 * 64 + kw + 4]; }
            if (ok1) { v10 = A2[(size_t)r1 * 64 + kw]; v11 = A2[(size_t)r1 * 64 + kw + 4]; }
            __nv_bfloat162 h; float2 f;
            h = __float22bfloat162_rn(v00); f = __bfloat1622float2(h);
            ah[0] = *reinterpret_cast<uint32_t*>(&h); al[0] = bf2_of(v00.x - f.x, v00.y - f.y);
            h = __float22bfloat162_rn(v10); f = __bfloat1622float2(h);
            ah[1] = *reinterpret_cast<uint32_t*>(&h); al[1] = bf2_of(v10.x - f.x, v10.y - f.y);
            h = __float22bfloat162_rn(v01); f = __bfloat1622float2(h);
            ah[2] = *reinterpret_cast<uint32_t*>(&h); al[2] = bf2_of(v01.x - f.x, v01.y - f.y);
            h = __float22bfloat162_rn(v11); f = __bfloat1622float2(h);
            ah[3] = *reinterpret_cast<uint32_t*>(&h); al[3] = bf2_of(v11.x - f.x, v11.y - f.y);
        }
        #pragma unroll
        for (int ni = 0; ni < 16; ni++) {
            int n = ni * 8 + fr;
            uint4 b = Wp[n * WPAD + kk * 4 + q];
            mma_bf16(acc[ni], ah[0], ah[1], ah[2], ah[3], b.x, b.y);      // A_hi * W_hi
            mma_bf16(acc[ni], ah[0], ah[1], ah[2], ah[3], b.z, b.w);      // A_hi * W_lo
            if (!FUSE)
                mma_bf16(acc[ni], al[0], al[1], al[2], al[3], b.x, b.y);  // A_lo * W_hi
        }
    }

    #pragma unroll
    for (int ni = 0; ni < 16; ni++) {
        int cw = ni * 4 + q;
        if (ok0) outb[(size_t)r0 * 64 + cw] = bf2_of(acc[ni][0], acc[ni][1]);
        if (ok1) outb[(size_t)r1 * 64 + cw] = bf2_of(acc[ni][2], acc[ni][3]);
    }
}

// ---- CSR aggregation, 4-way unrolled; fused bias+relu, bf16 out ----
__global__ __launch_bounds__(256) void k_agg(const uint2* __restrict__ hwb,
                                             const float* __restrict__ bias,
                                             uint2* __restrict__ hbf)
{
    int gid  = blockIdx.x * blockDim.x + threadIdx.x;
    int n    = gid >> 5;
    int lane = threadIdx.x & 31;
    if (n >= NN) return;
    uint2 sv = hwb[(size_t)n * 32 + lane];
    float2 s0 = bf2f(sv.x), s1 = bf2f(sv.y);
    float w = g_dinv2[n];
    float a0 = s0.x * w, a1 = s0.y * w, a2 = s1.x * w, a3 = s1.y * w;
    int i = g_off[n], end = g_off[n + 1];

    for (; i + 4 <= end; i += 4) {
        int   s0i = g_csrc[i],     s1i = g_csrc[i + 1];
        int   s2i = g_csrc[i + 2], s3i = g_csrc[i + 3];
        float w0 = g_cw[i],     w1 = g_cw[i + 1];
        float w2 = g_cw[i + 2], w3 = g_cw[i + 3];
        uint2 v0 = __ldg(&hwb[(size_t)s0i * 32 + lane]);
        uint2 v1 = __ldg(&hwb[(size_t)s1i * 32 + lane]);
        uint2 v2 = __ldg(&hwb[(size_t)s2i * 32 + lane]);
        uint2 v3 = __ldg(&hwb[(size_t)s3i * 32 + lane]);
        float2 f;
        f = bf2f(v0.x); a0 = fmaf(w0, f.x, a0); a1 = fmaf(w0, f.y, a1);
        f = bf2f(v0.y); a2 = fmaf(w0, f.x, a2); a3 = fmaf(w0, f.y, a3);
        f = bf2f(v1.x); a0 = fmaf(w1, f.x, a0); a1 = fmaf(w1, f.y, a1);
        f = bf2f(v1.y); a2 = fmaf(w1, f.x, a2); a3 = fmaf(w1, f.y, a3);
        f = bf2f(v2.x); a0 = fmaf(w2, f.x, a0); a1 = fmaf(w2, f.y, a1);
        f = bf2f(v2.y); a2 = fmaf(w2, f.x, a2); a3 = fmaf(w2, f.y, a3);
        f = bf2f(v3.x); a0 = fmaf(w3, f.x, a0); a1 = fmaf(w3, f.y, a1);
        f = bf2f(v3.y); a2 = fmaf(w3, f.x, a2); a3 = fmaf(w3, f.y, a3);
    }
    for (; i < end; i++) {
        int   sn = g_csrc[i];
        float we = g_cw[i];
        uint2 v  = __ldg(&hwb[(size_t)sn * 32 + lane]);
        float2 f0 = bf2f(v.x), f1 = bf2f(v.y);
        a0 = fmaf(we, f0.x, a0);
        a1 = fmaf(we, f0.y, a1);
        a2 = fmaf(we, f1.x, a2);
        a3 = fmaf(we, f1.y, a3);
    }
    float4 b4 = reinterpret_cast<const float4*>(bias)[lane];
    uint2 o;
    o.x = bf2_of(fmaxf(a0 + b4.x, 0.f), fmaxf(a1 + b4.y, 0.f));
    o.y = bf2_of(fmaxf(a2 + b4.z, 0.f), fmaxf(a3 + b4.w, 0.f));
    hbf[(size_t)n * 32 + lane] = o;
}

// ---------------- fused pool + MLP head: one block per graph ----------------
__global__ void k_pool_head(const uint32_t* __restrict__ hp,
                            const float* __restrict__ W1, const float* __restrict__ b1,
                            const float* __restrict__ W2, const float* __restrict__ b2,
                            const float* __restrict__ W3, const float* __restrict__ b3,
                            float* __restrict__ out)
{
    __shared__ float buf[128];
    __shared__ float partial[4];
    int g = blockIdx.x, c = threadIdx.x;
    int n0 = g_goff[g], n1 = g_goff[g + 1];
    int  wsel = c >> 1;
    bool hi   = c & 1;
    float acc = 0.f;
    for (int n = n0; n < n1; n++) {
        float2 hl = bf2f(hp[(size_t)n * 64 + wsel]);
        acc += hi ? hl.y : hl.x;
    }
    buf[c] = acc;
    __syncthreads();
    acc = b1[c];
    #pragma unroll 8
    for (int k = 0; k < 128; k++)
        acc = fmaf(buf[k], W1[k * 128 + c], acc);
    float z1 = fmaxf(acc, 0.f);
    __syncthreads();
    buf[c] = z1;
    __syncthreads();
    acc = b2[c];
    #pragma unroll 8
    for (int k = 0; k < 128; k++)
        acc = fmaf(buf[k], W2[k * 128 + c], acc);
    float z2 = fmaxf(acc, 0.f);
    float v = z2 * W3[c];
    #pragma unroll
    for (int o = 16; o > 0; o >>= 1) v += __shfl_down_sync(0xffffffffu, v, o);
    if ((c & 31) == 0) partial[c >> 5] = v;
    __syncthreads();
    if (c == 0) {
        float s = partial[0] + partial[1] + partial[2] + partial[3] + b3[0];
        out[g] = 1.f / (1.f + expf(-s));
    }
}

// ---------------- launch ----------------
extern "C" void kernel_launch(void* const* d_in, const int* in_sizes, int n_in,
                              void* d_out, int out_size)
{
    const float* x     = (const float*)d_in[0];
    const int*   ei    = (const int*)d_in[1];     // int32 (JAX x64 disabled)
    const int*   src   = ei;
    const int*   dst   = ei + NE;
    const int*   batch = (const int*)d_in[2];
    const float* convW = (const float*)d_in[3];
    const float* convB = (const float*)d_in[4];
    const float* W1    = (const float*)d_in[5];
    const float* b1    = (const float*)d_in[6];
    const float* W2    = (const float*)d_in[7];
    const float* b2    = (const float*)d_in[8];
    const float* W3    = (const float*)d_in[9];
    const float* b3    = (const float*)d_in[10];
    float* out = (float*)d_out;

    uint2 *hwb, *hbf;  uint4* wpk;
    cudaGetSymbolAddress((void**)&hwb, g_hwb);
    cudaGetSymbolAddress((void**)&hbf, g_hbf);
    cudaGetSymbolAddress((void**)&wpk, g_wpack);

    static cudaStream_t s2;
    static cudaEvent_t evFork, evJoin;
    static bool once = false;
    if (!once) {
        cudaFuncSetAttribute(k_gemm_mma<0>, cudaFuncAttributeMaxDynamicSharedMemorySize, SMEM_MMA);
        cudaFuncSetAttribute(k_gemm_mma<1>, cudaFuncAttributeMaxDynamicSharedMemorySize, SMEM_MMA);
        cudaStreamCreateWithFlags(&s2, cudaStreamNonBlocking);
        cudaEventCreateWithFlags(&evFork, cudaEventDisableTiming);
        cudaEventCreateWithFlags(&evJoin, cudaEventDisableTiming);
        once = true;
    }

    // ---- fork: CSR build (+goff) on side stream, W pack + gemm0 on main ----
    cudaEventRecord(evFork, 0);
    cudaStreamWaitEvent(s2, evFork, 0);

    k_cntzero<<<(NN + 255) / 256, 256, 0, s2>>>();
    k_cnt    <<<(NE + 255) / 256, 256, 0, s2>>>(dst);
    k_goff   <<<(NN + 256) / 256, 256, 0, s2>>>(batch);
    k_scan1  <<<NSB, SCAN_B, 0, s2>>>();
    k_scan3  <<<NSB, SCAN_B, 0, s2>>>();
    k_scatter<<<(NE + 255) / 256, 256, 0, s2>>>(src, dst);
    cudaEventRecord(evJoin, s2);

    uint32_t* hwb32 = reinterpret_cast<uint32_t*>(hwb);
    k_wpack<<<64, 256>>>(convW);
    k_gemm_mma<0><<<NTILES, 512, SMEM_MMA>>>(x, wpk, hwb32, NN);

    // ---- join, then the remaining dependent chain ----
    cudaStreamWaitEvent(0, evJoin, 0);
    k_agg<<<(NN * 32 + 255) / 256, 256>>>(hwb, convB, hbf);
    for (int l = 1; l < 4; l++) {
        k_gemm_mma<1><<<NTILES, 512, SMEM_MMA>>>(hbf, wpk + (size_t)l * 4096, hwb32, NN);
        k_agg<<<(NN * 32 + 255) / 256, 256>>>(hwb, convB + (size_t)l * DD, hbf);
    }

    // ---- fused pool + MLP head ----
    k_pool_head<<<NG, 128>>>(reinterpret_cast<const uint32_t*>(hbf),
                             W1, b1, W2, b2, W3, b3, out);
}